// round 1
// baseline (speedup 1.0000x reference)
#include <cuda_runtime.h>

// Problem constants (fixed by the reference):
//   ctrl_pts: (16, 64, 64, 4) f32     -> d_in[0]
//   uspan:    (512,) i32              -> d_in[1]
//   vspan:    (512,) i32              -> d_in[2]
//   Nu:       (512, 4) f32            -> d_in[3]
//   Nv:       (512, 4) f32            -> d_in[4]
//   out:      (16, 512, 512, 3) f32
#define BATCH   16
#define MCTRL   64
#define NCTRL   64
#define OUTN    512
#define PDEG    3

// Stage-A scratch: A[b][u][n][4] as float4 -> 16*512*64 float4 = 8 MiB (L2-resident)
__device__ float4 d_A[BATCH * OUTN * NCTRL];

// Stage A: A[b,u,n,:] = sum_r Nu[u,r] * ctrl[b, uspan[u]-3+r, n, :]
__global__ __launch_bounds__(256)
void surf_stageA(const float4* __restrict__ ctrl,
                 const int*    __restrict__ uspan,
                 const float*  __restrict__ Nu)
{
    int t = blockIdx.x * 256 + threadIdx.x;          // t in [0, 16*512*64)
    int n = t & (NCTRL - 1);
    int u = (t >> 6) & (OUTN - 1);
    int b = t >> 15;

    int iu0 = uspan[u] - PDEG;
    const float4* __restrict__ base = ctrl + ((b * MCTRL + iu0) * NCTRL + n);

    float nu0 = Nu[u * 4 + 0];
    float nu1 = Nu[u * 4 + 1];
    float nu2 = Nu[u * 4 + 2];
    float nu3 = Nu[u * 4 + 3];

    float4 c0 = __ldg(base + 0 * NCTRL);
    float4 c1 = __ldg(base + 1 * NCTRL);
    float4 c2 = __ldg(base + 2 * NCTRL);
    float4 c3 = __ldg(base + 3 * NCTRL);

    float4 acc;
    acc.x = nu0 * c0.x + nu1 * c1.x + nu2 * c2.x + nu3 * c3.x;
    acc.y = nu0 * c0.y + nu1 * c1.y + nu2 * c2.y + nu3 * c3.y;
    acc.z = nu0 * c0.z + nu1 * c1.z + nu2 * c2.z + nu3 * c3.z;
    acc.w = nu0 * c0.w + nu1 * c1.w + nu2 * c2.w + nu3 * c3.w;

    d_A[t] = acc;
}

// Stage B: Sw[b,u,v,:] = sum_s Nv[v,s] * A[b,u,vspan[v]-3+s,:]; out = Sw.xyz / Sw.w
__global__ __launch_bounds__(256)
void surf_stageB(const int*   __restrict__ vspan,
                 const float* __restrict__ Nv,
                 float*       __restrict__ out)
{
    int v = blockIdx.x * 256 + threadIdx.x;          // 2 blocks per (b,u) row
    int u = blockIdx.y;
    int b = blockIdx.z;

    int iv0 = vspan[v] - PDEG;
    const float4* __restrict__ base = d_A + ((b * OUTN + u) * NCTRL + iv0);

    float nv0 = Nv[v * 4 + 0];
    float nv1 = Nv[v * 4 + 1];
    float nv2 = Nv[v * 4 + 2];
    float nv3 = Nv[v * 4 + 3];

    float4 a0 = base[0];
    float4 a1 = base[1];
    float4 a2 = base[2];
    float4 a3 = base[3];

    float sx = nv0 * a0.x + nv1 * a1.x + nv2 * a2.x + nv3 * a3.x;
    float sy = nv0 * a0.y + nv1 * a1.y + nv2 * a2.y + nv3 * a3.y;
    float sz = nv0 * a0.z + nv1 * a1.z + nv2 * a2.z + nv3 * a3.z;
    float sw = nv0 * a0.w + nv1 * a1.w + nv2 * a2.w + nv3 * a3.w;

    float inv = 1.0f / sw;

    int o = ((b * OUTN + u) * OUTN + v) * 3;
    out[o + 0] = sx * inv;
    out[o + 1] = sy * inv;
    out[o + 2] = sz * inv;
}

extern "C" void kernel_launch(void* const* d_in, const int* in_sizes, int n_in,
                              void* d_out, int out_size)
{
    const float4* ctrl  = (const float4*)d_in[0];
    const int*    uspan = (const int*)   d_in[1];
    const int*    vspan = (const int*)   d_in[2];
    const float*  Nu    = (const float*) d_in[3];
    const float*  Nv    = (const float*) d_in[4];
    float*        out   = (float*)       d_out;

    // Stage A: 16*512*64 = 524288 threads
    surf_stageA<<<(BATCH * OUTN * NCTRL) / 256, 256>>>(ctrl, uspan, Nu);

    // Stage B: one thread per output point
    dim3 gridB(OUTN / 256, OUTN, BATCH);
    surf_stageB<<<gridB, 256>>>(vspan, Nv, out);
}

// round 2
// speedup vs baseline: 1.0976x; 1.0976x over previous
#include <cuda_runtime.h>

// Problem constants (fixed by the reference):
//   ctrl_pts: (16, 64, 64, 4) f32     -> d_in[0]
//   uspan:    (512,) i32              -> d_in[1]
//   vspan:    (512,) i32              -> d_in[2]
//   Nu:       (512, 4) f32            -> d_in[3]
//   Nv:       (512, 4) f32            -> d_in[4]
//   out:      (16, 512, 512, 3) f32
#define BATCH   16
#define MCTRL   64
#define NCTRL   64
#define OUTN    512
#define PDEG    3

// Stage-A scratch: A[b][u][n] as float4 -> 8 MiB (+ pad), L2-resident
__device__ float4 d_A[BATCH * OUTN * NCTRL + 8];

// ---------------------------------------------------------------------------
// Stage A: A[b,u,n,:] = sum_r Nu[u,r] * ctrl[b, uspan[u]-3+r, n, :]
// Each thread computes 4 consecutive u's for one n, using a 5-row window
// (span increments at most once within 4 consecutive u's).
// Block: 256 threads = 64 n  x  4 u-groups (16 u's per block).
// ---------------------------------------------------------------------------
__global__ __launch_bounds__(256)
void surf_stageA(const float4* __restrict__ ctrl,
                 const int*    __restrict__ uspan,
                 const float4* __restrict__ Nu4)
{
    int tid = threadIdx.x;
    int n   = tid & (NCTRL - 1);
    int g   = tid >> 6;                       // 0..3
    int b   = blockIdx.y;
    int u0  = blockIdx.x * 16 + g * 4;

    int4 us = __ldg((const int4*)uspan + (u0 >> 2));   // spans for u0..u0+3
    int iu0 = us.x - PDEG;

    const float4* __restrict__ base = ctrl + ((b * MCTRL + iu0) * NCTRL + n);
    float4 c0 = __ldg(base + 0 * NCTRL);
    float4 c1 = __ldg(base + 1 * NCTRL);
    float4 c2 = __ldg(base + 2 * NCTRL);
    float4 c3 = __ldg(base + 3 * NCTRL);
    float4 c4 = __ldg(base + 4 * NCTRL);

    int ds[4] = {0, us.y - us.x, us.z - us.x, us.w - us.x};

#pragma unroll
    for (int k = 0; k < 4; k++) {
        int u = u0 + k;
        float4 nu = __ldg(Nu4 + u);
        bool  d  = ds[k] != 0;                // 0 or 1
        float w0 = d ? 0.0f : nu.x;
        float w1 = d ? nu.x : nu.y;
        float w2 = d ? nu.y : nu.z;
        float w3 = d ? nu.z : nu.w;
        float w4 = d ? nu.w : 0.0f;

        float4 acc;
        acc.x = w0*c0.x + w1*c1.x + w2*c2.x + w3*c3.x + w4*c4.x;
        acc.y = w0*c0.y + w1*c1.y + w2*c2.y + w3*c3.y + w4*c4.y;
        acc.z = w0*c0.z + w1*c1.z + w2*c2.z + w3*c3.z + w4*c4.z;
        acc.w = w0*c0.w + w1*c1.w + w2*c2.w + w3*c3.w + w4*c4.w;

        d_A[(b * OUTN + u) * NCTRL + n] = acc;
    }
}

// ---------------------------------------------------------------------------
// Stage B: Sw[b,u,v,:] = sum_s Nv[v,s] * A[b,u,vspan[v]-3+s,:]
//          out = Sw.xyz / Sw.w
// Each thread computes 4 consecutive v's with a 5-element A window and
// writes 12 floats as 3x STG.128. Block = 128 threads = one (b,u) row.
// ---------------------------------------------------------------------------
__global__ __launch_bounds__(128)
void surf_stageB(const int*    __restrict__ vspan,
                 const float4* __restrict__ Nv4,
                 float4*       __restrict__ out)
{
    int t = threadIdx.x;          // 0..127, handles v = 4t .. 4t+3
    int u = blockIdx.x;
    int b = blockIdx.y;
    int v0 = t * 4;

    int4 vs = __ldg((const int4*)vspan + t);
    int iv0 = vs.x - PDEG;

    const float4* __restrict__ base = d_A + ((b * OUTN + u) * NCTRL + iv0);
    float4 a0 = base[0];
    float4 a1 = base[1];
    float4 a2 = base[2];
    float4 a3 = base[3];
    float4 a4 = base[4];

    int ds[4] = {0, vs.y - vs.x, vs.z - vs.x, vs.w - vs.x};

    float res[12];
#pragma unroll
    for (int k = 0; k < 4; k++) {
        float4 nv = __ldg(Nv4 + v0 + k);
        bool  d  = ds[k] != 0;
        float w0 = d ? 0.0f : nv.x;
        float w1 = d ? nv.x : nv.y;
        float w2 = d ? nv.y : nv.z;
        float w3 = d ? nv.z : nv.w;
        float w4 = d ? nv.w : 0.0f;

        float sx = w0*a0.x + w1*a1.x + w2*a2.x + w3*a3.x + w4*a4.x;
        float sy = w0*a0.y + w1*a1.y + w2*a2.y + w3*a3.y + w4*a4.y;
        float sz = w0*a0.z + w1*a1.z + w2*a2.z + w3*a3.z + w4*a4.z;
        float sw = w0*a0.w + w1*a1.w + w2*a2.w + w3*a3.w + w4*a4.w;

        float inv = 1.0f / sw;
        res[k*3 + 0] = sx * inv;
        res[k*3 + 1] = sy * inv;
        res[k*3 + 2] = sz * inv;
    }

    // Row of 512 outputs x 3 floats = 384 float4 per (b,u).
    float4* __restrict__ o = out + (size_t)(b * OUTN + u) * (OUTN * 3 / 4) + t * 3;
    o[0] = make_float4(res[0], res[1],  res[2],  res[3]);
    o[1] = make_float4(res[4], res[5],  res[6],  res[7]);
    o[2] = make_float4(res[8], res[9],  res[10], res[11]);
}

extern "C" void kernel_launch(void* const* d_in, const int* in_sizes, int n_in,
                              void* d_out, int out_size)
{
    const float4* ctrl  = (const float4*)d_in[0];
    const int*    uspan = (const int*)   d_in[1];
    const int*    vspan = (const int*)   d_in[2];
    const float4* Nu4   = (const float4*)d_in[3];
    const float4* Nv4   = (const float4*)d_in[4];
    float4*       out   = (float4*)      d_out;

    dim3 gridA(OUTN / 16, BATCH);          // 32 x 16 blocks, 256 threads
    surf_stageA<<<gridA, 256>>>(ctrl, uspan, Nu4);

    dim3 gridB(OUTN, BATCH);               // 512 x 16 blocks, 128 threads
    surf_stageB<<<gridB, 128>>>(vspan, Nv4, out);
}

// round 3
// speedup vs baseline: 1.1745x; 1.0701x over previous
#include <cuda_runtime.h>

// Problem constants:
//   ctrl_pts: (16, 64, 64, 4) f32, uspan/vspan: (512,) i32, Nu/Nv: (512,4) f32
//   out: (16, 512, 512, 3) f32
#define BATCH   16
#define MCTRL   64
#define NCTRL   64
#define OUTN    512
#define PDEG    3

// Stage-A scratch: A[b][u][n] as float4 -> 8 MiB, L2-resident
__device__ float4 d_A[BATCH * OUTN * NCTRL + 8];

// ---- packed f32x2 helpers ------------------------------------------------
__device__ __forceinline__ unsigned long long pack2(float a, float b) {
    unsigned long long r;
    asm("mov.b64 %0, {%1,%2};" : "=l"(r) : "f"(a), "f"(b));
    return r;
}
__device__ __forceinline__ void unpack2(unsigned long long v, float& a, float& b) {
    asm("mov.b64 {%0,%1}, %2;" : "=f"(a), "=f"(b) : "l"(v));
}
__device__ __forceinline__ unsigned long long mul2(unsigned long long a, unsigned long long b) {
    unsigned long long d;
    asm("mul.rn.f32x2 %0, %1, %2;" : "=l"(d) : "l"(a), "l"(b));
    return d;
}
__device__ __forceinline__ unsigned long long fma2(unsigned long long a, unsigned long long b,
                                                   unsigned long long c) {
    unsigned long long d;
    asm("fma.rn.f32x2 %0, %1, %2, %3;" : "=l"(d) : "l"(a), "l"(b), "l"(c));
    return d;
}
__device__ __forceinline__ float rcp_approx(float x) {
    float r;
    asm("rcp.approx.f32 %0, %1;" : "=f"(r) : "f"(x));
    return r;
}

// ---------------------------------------------------------------------------
// Stage A: A[b,u,n,:] = sum_r Nu[u,r] * ctrl[b, uspan[u]-3+r, n, :]
// Thread handles 8 consecutive u's for one n (span increments <=1 per 8
// samples since boundaries are >=8.6 samples apart) -> 5-row ctrl window.
// Block: 256 threads = 64 n x 4 groups-of-8-u (32 u per block).
// ---------------------------------------------------------------------------
__global__ __launch_bounds__(256)
void surf_stageA(const float4* __restrict__ ctrl,
                 const int4*   __restrict__ uspan4,
                 const float4* __restrict__ Nu4)
{
    int tid = threadIdx.x;
    int n   = tid & (NCTRL - 1);
    int grp = tid >> 6;                        // 0..3
    int b   = blockIdx.y;
    int u0  = (blockIdx.x * 4 + grp) * 8;

    int4 usA = __ldg(uspan4 + (u0 >> 2));
    int4 usB = __ldg(uspan4 + (u0 >> 2) + 1);
    int  s0  = usA.x;
    int  iu0 = s0 - PDEG;

    const float4* __restrict__ base = ctrl + ((b * MCTRL + iu0) * NCTRL + n);
    float4 c0 = __ldg(base + 0 * NCTRL);
    float4 c1 = __ldg(base + 1 * NCTRL);
    float4 c2 = __ldg(base + 2 * NCTRL);
    float4 c3 = __ldg(base + 3 * NCTRL);
    float4 c4 = __ldg(base + 4 * NCTRL);

    int d[8] = {0, usA.y - s0, usA.z - s0, usA.w - s0,
                usB.x - s0, usB.y - s0, usB.z - s0, usB.w - s0};

#pragma unroll
    for (int k = 0; k < 8; k++) {
        int u = u0 + k;
        float4 nu = __ldg(Nu4 + u);
        bool  sh = d[k] != 0;                  // shifted by one row
        float w0 = sh ? 0.0f : nu.x;
        float w1 = sh ? nu.x : nu.y;
        float w2 = sh ? nu.y : nu.z;
        float w3 = sh ? nu.z : nu.w;
        float w4 = sh ? nu.w : 0.0f;

        float4 acc;
        acc.x = w0*c0.x + w1*c1.x + w2*c2.x + w3*c3.x + w4*c4.x;
        acc.y = w0*c0.y + w1*c1.y + w2*c2.y + w3*c3.y + w4*c4.y;
        acc.z = w0*c0.z + w1*c1.z + w2*c2.z + w3*c3.z + w4*c4.z;
        acc.w = w0*c0.w + w1*c1.w + w2*c2.w + w3*c3.w + w4*c4.w;

        d_A[(b * OUTN + u) * NCTRL + n] = acc;
    }
}

// ---------------------------------------------------------------------------
// Stage B: out[b,u,v,:] = (sum_s Nv[v,s]*A[b,u,vspan[v]-3+s,:]).xyz / (.w)
// Block = 256 threads: g = t&127 is a fixed v-group (v=4g..4g+3),
// h = t>>7 selects row parity; loop covers 8 u-rows (u0+h+2i).
// Per-thread weights (5-window, f32x2-packed) computed ONCE for all rows.
// ---------------------------------------------------------------------------
__global__ __launch_bounds__(256)
void surf_stageB(const int4*   __restrict__ vspan4,
                 const float4* __restrict__ Nv4,
                 float4*       __restrict__ out)
{
    int t  = threadIdx.x;
    int g  = t & 127;               // v-group: v = 4g..4g+3
    int h  = t >> 7;                // row parity
    int b  = blockIdx.y;
    int u0 = blockIdx.x * 8;

    int4 vs  = __ldg(vspan4 + g);
    int  iv0 = vs.x - PDEG;
    int  dk[4] = {0, vs.y - vs.x, vs.z - vs.x, vs.w - vs.x};

    // Expand per-v 4-weights into shared 5-window, packed (w,w) for f32x2.
    unsigned long long wp[4][5];
#pragma unroll
    for (int k = 0; k < 4; k++) {
        float4 nv = __ldg(Nv4 + 4 * g + k);
        bool  sh = dk[k] != 0;
        float w0 = sh ? 0.0f : nv.x;
        float w1 = sh ? nv.x : nv.y;
        float w2 = sh ? nv.y : nv.z;
        float w3 = sh ? nv.z : nv.w;
        float w4 = sh ? nv.w : 0.0f;
        wp[k][0] = pack2(w0, w0);
        wp[k][1] = pack2(w1, w1);
        wp[k][2] = pack2(w2, w2);
        wp[k][3] = pack2(w3, w3);
        wp[k][4] = pack2(w4, w4);
    }

#pragma unroll
    for (int i = 0; i < 4; i++) {
        int u = u0 + h + 2 * i;

        const ulonglong2* __restrict__ Ab =
            (const ulonglong2*)(d_A + ((b * OUTN + u) * NCTRL + iv0));
        ulonglong2 a0 = Ab[0];
        ulonglong2 a1 = Ab[1];
        ulonglong2 a2 = Ab[2];
        ulonglong2 a3 = Ab[3];
        ulonglong2 a4 = Ab[4];

        float res[12];
#pragma unroll
        for (int k = 0; k < 4; k++) {
            unsigned long long axy = mul2(wp[k][0], a0.x);
            unsigned long long azw = mul2(wp[k][0], a0.y);
            axy = fma2(wp[k][1], a1.x, axy);
            azw = fma2(wp[k][1], a1.y, azw);
            axy = fma2(wp[k][2], a2.x, axy);
            azw = fma2(wp[k][2], a2.y, azw);
            axy = fma2(wp[k][3], a3.x, axy);
            azw = fma2(wp[k][3], a3.y, azw);
            axy = fma2(wp[k][4], a4.x, axy);
            azw = fma2(wp[k][4], a4.y, azw);

            float sx, sy, sz, sw;
            unpack2(axy, sx, sy);
            unpack2(azw, sz, sw);
            float inv = rcp_approx(sw);
            res[k * 3 + 0] = sx * inv;
            res[k * 3 + 1] = sy * inv;
            res[k * 3 + 2] = sz * inv;
        }

        float4* __restrict__ o =
            out + (size_t)(b * OUTN + u) * (OUTN * 3 / 4) + 3 * g;
        o[0] = make_float4(res[0], res[1],  res[2],  res[3]);
        o[1] = make_float4(res[4], res[5],  res[6],  res[7]);
        o[2] = make_float4(res[8], res[9],  res[10], res[11]);
    }
}

extern "C" void kernel_launch(void* const* d_in, const int* in_sizes, int n_in,
                              void* d_out, int out_size)
{
    const float4* ctrl   = (const float4*)d_in[0];
    const int4*   uspan4 = (const int4*)  d_in[1];
    const int4*   vspan4 = (const int4*)  d_in[2];
    const float4* Nu4    = (const float4*)d_in[3];
    const float4* Nv4    = (const float4*)d_in[4];
    float4*       out    = (float4*)      d_out;

    dim3 gridA(OUTN / 32, BATCH);          // 16 x 16 blocks, 256 threads
    surf_stageA<<<gridA, 256>>>(ctrl, uspan4, Nu4);

    dim3 gridB(OUTN / 8, BATCH);           // 64 x 16 blocks, 256 threads
    surf_stageB<<<gridB, 256>>>(vspan4, Nv4, out);
}

// round 4
// speedup vs baseline: 1.2877x; 1.0964x over previous
#include <cuda_runtime.h>

// ctrl_pts: (16,64,64,4) f32 | uspan/vspan: (512,) i32 | Nu/Nv: (512,4) f32
// out: (16,512,512,3) f32
#define BATCH   16
#define MCTRL   64
#define NCTRL   64
#define OUTN    512
#define PDEG    3

// ---- packed f32x2 helpers ------------------------------------------------
__device__ __forceinline__ unsigned long long pack2(float a, float b) {
    unsigned long long r;
    asm("mov.b64 %0, {%1,%2};" : "=l"(r) : "f"(a), "f"(b));
    return r;
}
__device__ __forceinline__ void unpack2(unsigned long long v, float& a, float& b) {
    asm("mov.b64 {%0,%1}, %2;" : "=f"(a), "=f"(b) : "l"(v));
}
__device__ __forceinline__ unsigned long long mul2(unsigned long long a, unsigned long long b) {
    unsigned long long d;
    asm("mul.rn.f32x2 %0, %1, %2;" : "=l"(d) : "l"(a), "l"(b));
    return d;
}
__device__ __forceinline__ unsigned long long fma2(unsigned long long a, unsigned long long b,
                                                   unsigned long long c) {
    unsigned long long d;
    asm("fma.rn.f32x2 %0, %1, %2, %3;" : "=l"(d) : "l"(a), "l"(b), "l"(c));
    return d;
}
__device__ __forceinline__ float rcp_approx(float x) {
    float r;
    asm("rcp.approx.f32 %0, %1;" : "=f"(r) : "f"(x));
    return r;
}

// ---------------------------------------------------------------------------
// Fused kernel. Block = (b, 8 u-rows). 256 threads.
// Phase 1: A[8][64] into smem:  A[u][n] = sum_r Nu[u,r]*ctrl[b,uspan[u]-3+r,n]
// Phase 2: out[b,u,v] = (sum_s Nv[v,s]*A[u,vspan[v]-3+s]).xyz / .w
//   g = t&127 owns v-group 4g..4g+3 (weights expanded once, reused 4 rows),
//   h = t>>7 row parity, rows u_local = h + 2i.
// ---------------------------------------------------------------------------
__global__ __launch_bounds__(256)
void surf_fused(const float4* __restrict__ ctrl,
                const int*    __restrict__ uspan,
                const int4*   __restrict__ vspan4,
                const float4* __restrict__ Nu4,
                const float4* __restrict__ Nv4,
                float4*       __restrict__ out)
{
    __shared__ float4 sA[8 * NCTRL];          // 8 KB

    int t  = threadIdx.x;
    int b  = blockIdx.y;
    int u0 = blockIdx.x * 8;

    // ---------------- Phase 1: build A tile ----------------
    {
        int n  = t & (NCTRL - 1);
        int up = t >> 6;                      // 0..3 ; handles up and up+4
#pragma unroll
        for (int half = 0; half < 2; half++) {
            int ul = up + 4 * half;
            int u  = u0 + ul;
            int iu0 = __ldg(uspan + u) - PDEG;
            const float4* __restrict__ base =
                ctrl + ((b * MCTRL + iu0) * NCTRL + n);
            float4 c0 = __ldg(base + 0 * NCTRL);
            float4 c1 = __ldg(base + 1 * NCTRL);
            float4 c2 = __ldg(base + 2 * NCTRL);
            float4 c3 = __ldg(base + 3 * NCTRL);
            float4 nu = __ldg(Nu4 + u);

            float4 acc;
            acc.x = nu.x*c0.x + nu.y*c1.x + nu.z*c2.x + nu.w*c3.x;
            acc.y = nu.x*c0.y + nu.y*c1.y + nu.z*c2.y + nu.w*c3.y;
            acc.z = nu.x*c0.z + nu.y*c1.z + nu.z*c2.z + nu.w*c3.z;
            acc.w = nu.x*c0.w + nu.y*c1.w + nu.z*c2.w + nu.w*c3.w;

            sA[ul * NCTRL + n] = acc;
        }
    }
    __syncthreads();

    // ---------------- Phase 2: evaluate 8 rows x 512 v ----------------
    int g = t & 127;                          // v-group: v = 4g..4g+3
    int h = t >> 7;                           // row parity

    int4 vs  = __ldg(vspan4 + g);
    int  iv0 = vs.x - PDEG;
    int  dk[4] = {0, vs.y - vs.x, vs.z - vs.x, vs.w - vs.x};

    unsigned long long wp[4][5];
#pragma unroll
    for (int k = 0; k < 4; k++) {
        float4 nv = __ldg(Nv4 + 4 * g + k);
        bool  sh = dk[k] != 0;
        float w0 = sh ? 0.0f : nv.x;
        float w1 = sh ? nv.x : nv.y;
        float w2 = sh ? nv.y : nv.z;
        float w3 = sh ? nv.z : nv.w;
        float w4 = sh ? nv.w : 0.0f;
        wp[k][0] = pack2(w0, w0);
        wp[k][1] = pack2(w1, w1);
        wp[k][2] = pack2(w2, w2);
        wp[k][3] = pack2(w3, w3);
        wp[k][4] = pack2(w4, w4);
    }

#pragma unroll
    for (int i = 0; i < 4; i++) {
        int ul = h + 2 * i;
        int u  = u0 + ul;

        const ulonglong2* __restrict__ Ab =
            (const ulonglong2*)(sA + ul * NCTRL + iv0);
        ulonglong2 a0 = Ab[0];
        ulonglong2 a1 = Ab[1];
        ulonglong2 a2 = Ab[2];
        ulonglong2 a3 = Ab[3];
        ulonglong2 a4 = Ab[4];

        float res[12];
#pragma unroll
        for (int k = 0; k < 4; k++) {
            unsigned long long axy = mul2(wp[k][0], a0.x);
            unsigned long long azw = mul2(wp[k][0], a0.y);
            axy = fma2(wp[k][1], a1.x, axy);
            azw = fma2(wp[k][1], a1.y, azw);
            axy = fma2(wp[k][2], a2.x, axy);
            azw = fma2(wp[k][2], a2.y, azw);
            axy = fma2(wp[k][3], a3.x, axy);
            azw = fma2(wp[k][3], a3.y, azw);
            axy = fma2(wp[k][4], a4.x, axy);
            azw = fma2(wp[k][4], a4.y, azw);

            float sx, sy, sz, sw;
            unpack2(axy, sx, sy);
            unpack2(azw, sz, sw);
            float inv = rcp_approx(sw);
            res[k * 3 + 0] = sx * inv;
            res[k * 3 + 1] = sy * inv;
            res[k * 3 + 2] = sz * inv;
        }

        float4* __restrict__ o =
            out + (size_t)(b * OUTN + u) * (OUTN * 3 / 4) + 3 * g;
        o[0] = make_float4(res[0], res[1],  res[2],  res[3]);
        o[1] = make_float4(res[4], res[5],  res[6],  res[7]);
        o[2] = make_float4(res[8], res[9],  res[10], res[11]);
    }
}

extern "C" void kernel_launch(void* const* d_in, const int* in_sizes, int n_in,
                              void* d_out, int out_size)
{
    const float4* ctrl   = (const float4*)d_in[0];
    const int*    uspan  = (const int*)   d_in[1];
    const int4*   vspan4 = (const int4*)  d_in[2];
    const float4* Nu4    = (const float4*)d_in[3];
    const float4* Nv4    = (const float4*)d_in[4];
    float4*       out    = (float4*)      d_out;

    dim3 grid(OUTN / 8, BATCH);               // 64 x 16 = 1024 blocks
    surf_fused<<<grid, 256>>>(ctrl, uspan, vspan4, Nu4, Nv4, out);
}

// round 5
// speedup vs baseline: 1.4274x; 1.1085x over previous
#include <cuda_runtime.h>

// ctrl_pts: (16,64,64,4) f32 | uspan/vspan: (512,) i32 | Nu/Nv: (512,4) f32
// out: (16,512,512,3) f32
#define BATCH   16
#define MCTRL   64
#define NCTRL   64
#define OUTN    512
#define PDEG    3

// ---- packed f32x2 helpers ------------------------------------------------
__device__ __forceinline__ unsigned long long pack2(float a, float b) {
    unsigned long long r;
    asm("mov.b64 %0, {%1,%2};" : "=l"(r) : "f"(a), "f"(b));
    return r;
}
__device__ __forceinline__ void unpack2(unsigned long long v, float& a, float& b) {
    asm("mov.b64 {%0,%1}, %2;" : "=f"(a), "=f"(b) : "l"(v));
}
__device__ __forceinline__ unsigned long long mul2(unsigned long long a, unsigned long long b) {
    unsigned long long d;
    asm("mul.rn.f32x2 %0, %1, %2;" : "=l"(d) : "l"(a), "l"(b));
    return d;
}
__device__ __forceinline__ unsigned long long fma2(unsigned long long a, unsigned long long b,
                                                   unsigned long long c) {
    unsigned long long d;
    asm("fma.rn.f32x2 %0, %1, %2, %3;" : "=l"(d) : "l"(a), "l"(b), "l"(c));
    return d;
}
__device__ __forceinline__ float rcp_approx(float x) {
    float r;
    asm("rcp.approx.f32 %0, %1;" : "=f"(r) : "f"(x));
    return r;
}

// ---------------------------------------------------------------------------
// Fused kernel. Block = (b, 4 u-rows), 128 threads, 6 blocks/SM.
// Phase 1: A[4][64] into smem.
// Phase 2: thread g owns v-group 4g..4g+3 (weights expanded once into a
//          5-window, f32x2-packed), loops over the 4 u-rows.
// ---------------------------------------------------------------------------
__global__ __launch_bounds__(128, 6)
void surf_fused(const float4* __restrict__ ctrl,
                const int*    __restrict__ uspan,
                const int4*   __restrict__ vspan4,
                const float4* __restrict__ Nu4,
                const float4* __restrict__ Nv4,
                float4*       __restrict__ out)
{
    __shared__ float4 sA[4 * NCTRL];          // 4 KB

    int t  = threadIdx.x;                     // 0..127
    int b  = blockIdx.y;
    int u0 = blockIdx.x * 4;

    // ---------------- Phase 1: build A tile (4 rows x 64 n) ----------------
    {
        int n  = t & (NCTRL - 1);
        int up = t >> 6;                      // 0..1 ; handles up and up+2
#pragma unroll
        for (int half = 0; half < 2; half++) {
            int ul = up + 2 * half;
            int u  = u0 + ul;
            int iu0 = __ldg(uspan + u) - PDEG;
            const float4* __restrict__ base =
                ctrl + ((b * MCTRL + iu0) * NCTRL + n);
            float4 c0 = __ldg(base + 0 * NCTRL);
            float4 c1 = __ldg(base + 1 * NCTRL);
            float4 c2 = __ldg(base + 2 * NCTRL);
            float4 c3 = __ldg(base + 3 * NCTRL);
            float4 nu = __ldg(Nu4 + u);

            float4 acc;
            acc.x = nu.x*c0.x + nu.y*c1.x + nu.z*c2.x + nu.w*c3.x;
            acc.y = nu.x*c0.y + nu.y*c1.y + nu.z*c2.y + nu.w*c3.y;
            acc.z = nu.x*c0.z + nu.y*c1.z + nu.z*c2.z + nu.w*c3.z;
            acc.w = nu.x*c0.w + nu.y*c1.w + nu.z*c2.w + nu.w*c3.w;

            sA[ul * NCTRL + n] = acc;
        }
    }
    __syncthreads();

    // ---------------- Phase 2: evaluate 4 rows x 512 v ----------------
    int g = t;                                // v-group: v = 4g..4g+3

    int4 vs  = __ldg(vspan4 + g);
    int  iv0 = vs.x - PDEG;
    int  dk[4] = {0, vs.y - vs.x, vs.z - vs.x, vs.w - vs.x};

    unsigned long long wp[4][5];
#pragma unroll
    for (int k = 0; k < 4; k++) {
        float4 nv = __ldg(Nv4 + 4 * g + k);
        bool  sh = dk[k] != 0;
        float w0 = sh ? 0.0f : nv.x;
        float w1 = sh ? nv.x : nv.y;
        float w2 = sh ? nv.y : nv.z;
        float w3 = sh ? nv.z : nv.w;
        float w4 = sh ? nv.w : 0.0f;
        wp[k][0] = pack2(w0, w0);
        wp[k][1] = pack2(w1, w1);
        wp[k][2] = pack2(w2, w2);
        wp[k][3] = pack2(w3, w3);
        wp[k][4] = pack2(w4, w4);
    }

#pragma unroll
    for (int i = 0; i < 4; i++) {
        int u = u0 + i;

        const ulonglong2* __restrict__ Ab =
            (const ulonglong2*)(sA + i * NCTRL + iv0);
        ulonglong2 a0 = Ab[0];
        ulonglong2 a1 = Ab[1];
        ulonglong2 a2 = Ab[2];
        ulonglong2 a3 = Ab[3];
        ulonglong2 a4 = Ab[4];

        float res[12];
#pragma unroll
        for (int k = 0; k < 4; k++) {
            unsigned long long axy = mul2(wp[k][0], a0.x);
            unsigned long long azw = mul2(wp[k][0], a0.y);
            axy = fma2(wp[k][1], a1.x, axy);
            azw = fma2(wp[k][1], a1.y, azw);
            axy = fma2(wp[k][2], a2.x, axy);
            azw = fma2(wp[k][2], a2.y, azw);
            axy = fma2(wp[k][3], a3.x, axy);
            azw = fma2(wp[k][3], a3.y, azw);
            axy = fma2(wp[k][4], a4.x, axy);
            azw = fma2(wp[k][4], a4.y, azw);

            float sx, sy, sz, sw;
            unpack2(axy, sx, sy);
            unpack2(azw, sz, sw);
            float inv = rcp_approx(sw);
            res[k * 3 + 0] = sx * inv;
            res[k * 3 + 1] = sy * inv;
            res[k * 3 + 2] = sz * inv;
        }

        float4* __restrict__ o =
            out + (size_t)(b * OUTN + u) * (OUTN * 3 / 4) + 3 * g;
        o[0] = make_float4(res[0], res[1],  res[2],  res[3]);
        o[1] = make_float4(res[4], res[5],  res[6],  res[7]);
        o[2] = make_float4(res[8], res[9],  res[10], res[11]);
    }
}

extern "C" void kernel_launch(void* const* d_in, const int* in_sizes, int n_in,
                              void* d_out, int out_size)
{
    const float4* ctrl   = (const float4*)d_in[0];
    const int*    uspan  = (const int*)   d_in[1];
    const int4*   vspan4 = (const int4*)  d_in[2];
    const float4* Nu4    = (const float4*)d_in[3];
    const float4* Nv4    = (const float4*)d_in[4];
    float4*       out    = (float4*)      d_out;

    dim3 grid(OUTN / 4, BATCH);               // 128 x 16 = 2048 blocks
    surf_fused<<<grid, 128>>>(ctrl, uspan, vspan4, Nu4, Nv4, out);
}